// round 4
// baseline (speedup 1.0000x reference)
#include <cuda_runtime.h>
#include <cstdint>

// ScaledDotProductAttention: B=2,H=16,S=2048,D=64, causal, fp32 in/out.
// FlashAttention-2, tf32 mma.sync m16n8k8. m32 per warp (two m16 tiles) so
// each K/V B-fragment load feeds 2 MMAs -> smem crossbar bytes halved vs R1.
// CTA = 128 q-rows, 4 warps, BN=64 key tiles. tcgen05 unavailable (harness
// PTX targets compute_103 without 'a').

#define S_LEN 2048
#define DH 64
#define BM 128
#define BN 64
#define LOG2E 1.4426950408889634f

__device__ __forceinline__ uint32_t f2tf32(float f) {
    uint32_t u;
    asm("cvt.rna.tf32.f32 %0, %1;" : "=r"(u) : "f"(f));
    return u;
}

__device__ __forceinline__ void mma_tf32(float c[4],
                                         uint32_t a0, uint32_t a1, uint32_t a2, uint32_t a3,
                                         uint32_t b0, uint32_t b1) {
    asm volatile(
        "mma.sync.aligned.m16n8k8.row.col.f32.tf32.tf32.f32 "
        "{%0,%1,%2,%3}, {%4,%5,%6,%7}, {%8,%9}, {%0,%1,%2,%3};"
        : "+f"(c[0]), "+f"(c[1]), "+f"(c[2]), "+f"(c[3])
        : "r"(a0), "r"(a1), "r"(a2), "r"(a3), "r"(b0), "r"(b1));
}

__global__ void __launch_bounds__(128)
fa_tf32_m32_kernel(const float* __restrict__ Q, const float* __restrict__ K,
                   const float* __restrict__ V, float* __restrict__ O)
{
    // Conflict-free padded strides (validated in R1):
    //   sK stride 68: b-frag bank = 4g + t  (32 distinct)
    //   sV stride 72: b-frag bank = 8t + g  (32 distinct)
    __shared__ uint32_t sK[BN][68];
    __shared__ uint32_t sV[BN][72];

    const int qt   = gridDim.x - 1 - blockIdx.x;   // heavy tiles first
    const int bh   = blockIdx.y;
    const int tid  = threadIdx.x;
    const int wid  = tid >> 5;
    const int lane = tid & 31;
    const int g    = lane >> 2;
    const int t    = lane & 3;

    const size_t base = (size_t)bh * S_LEN * DH;
    const float* Qb = Q + base;
    const float* Kb = K + base;
    const float* Vb = V + base;
    float*       Ob = O + base;

    const int q0 = qt * BM;
    const int nt = 2 * qt + 2;                     // 64-key tiles (causal)
    // Warp owns rows [q0 + wid*32, +32): two m16 halves h=0,1.
    int rowh[2];
    rowh[0] = q0 + wid * 32 + g;                   // rows rowh, rowh+8
    rowh[1] = rowh[0] + 16;
    const int wrow_max = q0 + wid * 32 + 31;

    // --- Q fragments, pre-scaled by log2(e)/sqrt(D), tf32 ---
    uint32_t aQ[2][8][4];
    const float qscale = LOG2E * 0.125f;
    #pragma unroll
    for (int h = 0; h < 2; h++) {
        #pragma unroll
        for (int k8 = 0; k8 < 8; k8++) {
            aQ[h][k8][0] = f2tf32(Qb[(size_t)(rowh[h])     * DH + 8*k8 + t    ] * qscale);
            aQ[h][k8][1] = f2tf32(Qb[(size_t)(rowh[h] + 8) * DH + 8*k8 + t    ] * qscale);
            aQ[h][k8][2] = f2tf32(Qb[(size_t)(rowh[h])     * DH + 8*k8 + t + 4] * qscale);
            aQ[h][k8][3] = f2tf32(Qb[(size_t)(rowh[h] + 8) * DH + 8*k8 + t + 4] * qscale);
        }
    }

    // Output accumulators + online softmax state (per half, per row-class)
    float o[2][8][4];
    #pragma unroll
    for (int h = 0; h < 2; h++)
        #pragma unroll
        for (int n = 0; n < 8; n++)
            o[h][n][0] = o[h][n][1] = o[h][n][2] = o[h][n][3] = 0.f;
    float mst[2][2], lst[2][2];
    #pragma unroll
    for (int h = 0; h < 2; h++) {
        mst[h][0] = mst[h][1] = -INFINITY;
        lst[h][0] = lst[h][1] = 0.f;
    }

    // Shuffle sources for P(C-layout) -> A-fragment re-layout (validated in R1)
    const int srcA = (lane & 28) | (t >> 1);
    const int srcB = srcA + 2;
    const bool odd = (t & 1);

    for (int kt = 0; kt < nt; kt++) {
        const int k0 = kt * BN;

        // ---- stage K,V tile (tf32-converted) ----
        #pragma unroll
        for (int i = 0; i < 8; i++) {
            int lin = (i << 7) + tid;
            int r   = lin & 63;
            int c4  = (lin >> 6) << 2;
            const float4 kf = *reinterpret_cast<const float4*>(&Kb[(size_t)(k0 + r) * DH + c4]);
            const float4 vf = *reinterpret_cast<const float4*>(&Vb[(size_t)(k0 + r) * DH + c4]);
            uint4 ku = make_uint4(f2tf32(kf.x), f2tf32(kf.y), f2tf32(kf.z), f2tf32(kf.w));
            uint4 vu = make_uint4(f2tf32(vf.x), f2tf32(vf.y), f2tf32(vf.z), f2tf32(vf.w));
            *reinterpret_cast<uint4*>(&sK[r][c4]) = ku;
            *reinterpret_cast<uint4*>(&sV[r][c4]) = vu;
        }
        __syncthreads();

        if (k0 <= wrow_max) {   // tile not fully masked for this warp
            // ---- S = Q K^T : each B-frag pair feeds both m16 halves ----
            float c[2][8][4];
            #pragma unroll
            for (int h = 0; h < 2; h++)
                #pragma unroll
                for (int n = 0; n < 8; n++)
                    c[h][n][0] = c[h][n][1] = c[h][n][2] = c[h][n][3] = 0.f;
            #pragma unroll
            for (int n = 0; n < 8; n++) {
                #pragma unroll
                for (int k8 = 0; k8 < 8; k8++) {
                    uint32_t b0 = sK[8*n + g][8*k8 + t];
                    uint32_t b1 = sK[8*n + g][8*k8 + t + 4];
                    mma_tf32(c[0][n], aQ[0][k8][0], aQ[0][k8][1], aQ[0][k8][2], aQ[0][k8][3], b0, b1);
                    mma_tf32(c[1][n], aQ[1][k8][0], aQ[1][k8][1], aQ[1][k8][2], aQ[1][k8][3], b0, b1);
                }
            }

            // ---- causal mask (only tiles crossing a diagonal) ----
            #pragma unroll
            for (int h = 0; h < 2; h++) {
                if (k0 + 63 > rowh[h]) {
                    #pragma unroll
                    for (int n = 0; n < 8; n++) {
                        int j0 = k0 + 8*n + 2*t;
                        if (j0     > rowh[h])     c[h][n][0] = -1e30f;
                        if (j0 + 1 > rowh[h])     c[h][n][1] = -1e30f;
                        if (j0     > rowh[h] + 8) c[h][n][2] = -1e30f;
                        if (j0 + 1 > rowh[h] + 8) c[h][n][3] = -1e30f;
                    }
                }
            }

            // ---- online softmax per half ----
            float al[2][2];
            #pragma unroll
            for (int h = 0; h < 2; h++) {
                float tm0 = -INFINITY, tm1 = -INFINITY;
                #pragma unroll
                for (int n = 0; n < 8; n++) {
                    tm0 = fmaxf(tm0, fmaxf(c[h][n][0], c[h][n][1]));
                    tm1 = fmaxf(tm1, fmaxf(c[h][n][2], c[h][n][3]));
                }
                tm0 = fmaxf(tm0, __shfl_xor_sync(0xffffffffu, tm0, 1));
                tm0 = fmaxf(tm0, __shfl_xor_sync(0xffffffffu, tm0, 2));
                tm1 = fmaxf(tm1, __shfl_xor_sync(0xffffffffu, tm1, 1));
                tm1 = fmaxf(tm1, __shfl_xor_sync(0xffffffffu, tm1, 2));

                const float mn0 = fmaxf(mst[h][0], tm0);
                const float mn1 = fmaxf(mst[h][1], tm1);
                al[h][0] = exp2f(mst[h][0] - mn0);
                al[h][1] = exp2f(mst[h][1] - mn1);

                float sp0 = 0.f, sp1 = 0.f;
                #pragma unroll
                for (int n = 0; n < 8; n++) {
                    float p0 = exp2f(c[h][n][0] - mn0);
                    float p1 = exp2f(c[h][n][1] - mn0);
                    float p2 = exp2f(c[h][n][2] - mn1);
                    float p3 = exp2f(c[h][n][3] - mn1);
                    sp0 += p0 + p1;
                    sp1 += p2 + p3;
                    c[h][n][0] = __uint_as_float(f2tf32(p0));
                    c[h][n][1] = __uint_as_float(f2tf32(p1));
                    c[h][n][2] = __uint_as_float(f2tf32(p2));
                    c[h][n][3] = __uint_as_float(f2tf32(p3));
                }
                sp0 += __shfl_xor_sync(0xffffffffu, sp0, 1);
                sp0 += __shfl_xor_sync(0xffffffffu, sp0, 2);
                sp1 += __shfl_xor_sync(0xffffffffu, sp1, 1);
                sp1 += __shfl_xor_sync(0xffffffffu, sp1, 2);

                lst[h][0] = lst[h][0] * al[h][0] + sp0;
                lst[h][1] = lst[h][1] * al[h][1] + sp1;
                mst[h][0] = mn0;
                mst[h][1] = mn1;

                #pragma unroll
                for (int n = 0; n < 8; n++) {
                    o[h][n][0] *= al[h][0]; o[h][n][1] *= al[h][0];
                    o[h][n][2] *= al[h][1]; o[h][n][3] *= al[h][1];
                }
            }

            // ---- O += P V : B-frag pair feeds both halves ----
            #pragma unroll
            for (int kk = 0; kk < 8; kk++) {
                uint32_t a[2][4];
                #pragma unroll
                for (int h = 0; h < 2; h++) {
                    float x0 = __shfl_sync(0xffffffffu, c[h][kk][0], srcA);
                    float x1 = __shfl_sync(0xffffffffu, c[h][kk][1], srcA);
                    float y0 = __shfl_sync(0xffffffffu, c[h][kk][0], srcB);
                    float y1 = __shfl_sync(0xffffffffu, c[h][kk][1], srcB);
                    float z0 = __shfl_sync(0xffffffffu, c[h][kk][2], srcA);
                    float z1 = __shfl_sync(0xffffffffu, c[h][kk][3], srcA);
                    float w0 = __shfl_sync(0xffffffffu, c[h][kk][2], srcB);
                    float w1 = __shfl_sync(0xffffffffu, c[h][kk][3], srcB);
                    a[h][0] = __float_as_uint(odd ? x1 : x0);
                    a[h][1] = __float_as_uint(odd ? z1 : z0);
                    a[h][2] = __float_as_uint(odd ? y1 : y0);
                    a[h][3] = __float_as_uint(odd ? w1 : w0);
                }
                #pragma unroll
                for (int n = 0; n < 8; n++) {
                    uint32_t b0 = sV[8*kk + t    ][8*n + g];
                    uint32_t b1 = sV[8*kk + t + 4][8*n + g];
                    mma_tf32(o[0][n], a[0][0], a[0][1], a[0][2], a[0][3], b0, b1);
                    mma_tf32(o[1][n], a[1][0], a[1][1], a[1][2], a[1][3], b0, b1);
                }
            }
        }
        __syncthreads();
    }

    // ---- epilogue ----
    #pragma unroll
    for (int h = 0; h < 2; h++) {
        const float il0 = 1.0f / lst[h][0];
        const float il1 = 1.0f / lst[h][1];
        #pragma unroll
        for (int n = 0; n < 8; n++) {
            float2 r0v = make_float2(o[h][n][0] * il0, o[h][n][1] * il0);
            float2 r1v = make_float2(o[h][n][2] * il1, o[h][n][3] * il1);
            *reinterpret_cast<float2*>(&Ob[(size_t)(rowh[h])     * DH + 8*n + 2*t]) = r0v;
            *reinterpret_cast<float2*>(&Ob[(size_t)(rowh[h] + 8) * DH + 8*n + 2*t]) = r1v;
        }
    }
}

extern "C" void kernel_launch(void* const* d_in, const int* in_sizes, int n_in,
                              void* d_out, int out_size) {
    const float* q = (const float*)d_in[0];
    const float* k = (const float*)d_in[1];
    const float* v = (const float*)d_in[2];
    // d_in[3] = causal_mask: exactly lower-triangular, handled analytically.
    float* o = (float*)d_out;

    dim3 grid(S_LEN / BM, 2 * 16);   // (16, 32)
    fa_tf32_m32_kernel<<<grid, 128>>>(q, k, v, o);
}